// round 13
// baseline (speedup 1.0000x reference)
#include <cuda_runtime.h>
#include <cuda_bf16.h>
#include <math.h>
#include <stdint.h>
#include <stddef.h>

#define Bq 16
#define Cq 768
#define Nq 1024
#define Hh 8
#define Chq 96
#define HIDq 3072
#define NMODE 56
#define NROWS (Bq*Nq)
#define WPSZ ((size_t)NMODE*Cq*Cq)

__device__ float g_mean[NROWS];
__device__ float g_rstd[NROWS];
__device__ float g_tln [(size_t)NROWS*Cq];
__device__ float g_dftr[(size_t)Bq*Cq*32*4];
__device__ float g_dfti[(size_t)Bq*Cq*32*4];
__device__ float g_xfr [(size_t)NMODE*Bq*Cq];
__device__ float g_xfi [(size_t)NMODE*Bq*Cq];
__device__ float g_ofr [(size_t)Bq*Cq*NMODE];
__device__ float g_ofi [(size_t)Bq*Cq*NMODE];
__device__ float g_fimg[(size_t)Bq*Cq*Nq];
__device__ float g_qkv [(size_t)NROWS*3*Cq];
__device__ float g_kmax[Bq*Cq];
__device__ float g_krcp[Bq*Cq];
__device__ float g_kv  [(size_t)Bq*Hh*Chq*Chq];
__device__ float g_vimg[(size_t)Bq*Cq*Nq];
__device__ float g_cv  [(size_t)Bq*Cq*Nq];
__device__ float g_tres[(size_t)NROWS*Cq];
__device__ float g_uln [(size_t)NROWS*Cq];
__device__ float g_u1  [(size_t)NROWS*HIDq];
__device__ float g_u1g [(size_t)NROWS*HIDq];
__device__ float g_u2  [(size_t)NROWS*Cq];
__device__ float g_wpr [2][WPSZ];
__device__ float g_wpi [2][WPSZ];
__device__ __nv_bfloat16 g_ah[(size_t)NROWS*HIDq];
__device__ __nv_bfloat16 g_al[(size_t)NROWS*HIDq];
__device__ __nv_bfloat16 g_wh[(size_t)HIDq*Cq];
__device__ __nv_bfloat16 g_wl[(size_t)HIDq*Cq];

__device__ __forceinline__ void split_write(__nv_bfloat16* dh, __nv_bfloat16* dl, size_t idx, float x){
    __nv_bfloat16 hh = __float2bfloat16(x);
    dh[idx] = hh;
    dl[idx] = __float2bfloat16(x - __bfloat162float(hh));
}

__global__ __launch_bounds__(256) void k_repack(const float* __restrict__ w, int conv, int ri, int mh0){
    float* dst = ri ? g_wpi[conv] : g_wpr[conv];
    int ic = blockIdx.x, oc = blockIdx.y*256 + threadIdx.x;
    const float* s = w + ((size_t)ic*Cq + oc)*28;
    float v[28];
#pragma unroll
    for (int k = 0; k < 28; k++) v[k] = s[k];
#pragma unroll
    for (int m1 = 0; m1 < 7; m1++)
#pragma unroll
        for (int kw = 0; kw < 4; kw++)
            dst[((size_t)((mh0+m1)*4+kw)*Cq + ic)*Cq + oc] = v[m1*4+kw];
}

__global__ __launch_bounds__(256) void k_wsplit(const float* __restrict__ w, size_t n){
    size_t i = (size_t)blockIdx.x*256 + threadIdx.x;
    if (i < n){
        float x = w[i];
        split_write(g_wh, g_wl, i, x);
    }
}

__global__ __launch_bounds__(256) void k_ln1_stats(const float* __restrict__ x){
    int b = blockIdx.x, n = blockIdx.y*256 + threadIdx.x;
    const float* p = x + ((size_t)b*Cq << 10) + n;
    float s = 0.f, s2 = 0.f;
#pragma unroll 4
    for (int c = 0; c < Cq; c++){ float v = p[(size_t)c << 10]; s += v; s2 += v*v; }
    float m = s*(1.f/Cq);
    g_mean[(b<<10)+n] = m;
    g_rstd[(b<<10)+n] = rsqrtf(s2*(1.f/Cq) - m*m + 1e-5f);
}

__global__ void k_lnT(const float* __restrict__ x, const float* __restrict__ g, const float* __restrict__ be){
    __shared__ float tile[32][33];
    int b = blockIdx.x, n0 = blockIdx.y*32, c0 = blockIdx.z*32;
    int tx = threadIdx.x, ty = threadIdx.y;
#pragma unroll
    for (int j = 0; j < 4; j++)
        tile[ty+j*8][tx] = x[((size_t)(b*Cq + c0+ty+j*8) << 10) + n0 + tx];
    __syncthreads();
#pragma unroll
    for (int j = 0; j < 4; j++){
        int n = n0+ty+j*8, c = c0+tx;
        float m = g_mean[(b<<10)+n], r = g_rstd[(b<<10)+n];
        g_tln[((size_t)(b<<10)+n)*Cq + c] = (tile[tx][ty+j*8]-m)*r*g[c] + be[c];
    }
}

__global__ __launch_bounds__(256) void k_dft_w(const float* __restrict__ xext,
                                               const float* __restrict__ lg, const float* __restrict__ lb,
                                               int do_ln){
    __shared__ float tc[32], ts[32];
    if (threadIdx.x < 32){ float a = 6.283185307179586f*threadIdx.x/32.f; tc[threadIdx.x]=cosf(a); ts[threadIdx.x]=sinf(a); }
    __syncthreads();
    int gid = blockIdx.x*256 + threadIdx.x;
    int h = gid & 31, bc = gid >> 5;
    int c = bc % Cq, b = bc / Cq;
    const float* src = do_ln ? xext : g_vimg;
    const float* row = src + ((size_t)bc << 10) + (h << 5);
    float ar[4] = {0,0,0,0}, ai[4] = {0,0,0,0};
    float gc = do_ln ? lg[c] : 0.f, bcv = do_ln ? lb[c] : 0.f;
    int nb = (b<<10) + (h<<5);
    for (int w = 0; w < 32; w++){
        float v = row[w];
        if (do_ln) v = (v - g_mean[nb+w])*g_rstd[nb+w]*gc + bcv;
        ar[0] += v;
#pragma unroll
        for (int kw = 1; kw < 4; kw++){
            int ix = (kw*w)&31;
            ar[kw] += v*tc[ix]; ai[kw] -= v*ts[ix];
        }
    }
    size_t o = (size_t)gid << 2;
#pragma unroll
    for (int kw = 0; kw < 4; kw++){ g_dftr[o+kw]=ar[kw]; g_dfti[o+kw]=ai[kw]; }
}

__global__ __launch_bounds__(256) void k_dft_h(){
    __shared__ float tc[32], ts[32];
    if (threadIdx.x < 32){ float a = 6.283185307179586f*threadIdx.x/32.f; tc[threadIdx.x]=cosf(a); ts[threadIdx.x]=sinf(a); }
    __syncthreads();
    int gid = blockIdx.x*256 + threadIdx.x;
    int c = gid % Cq, mh = (gid/Cq) % 14, b = gid/(Cq*14);
    int kh = (mh < 7) ? mh : mh + 18;
    const float* zr = g_dftr + (size_t)(b*Cq+c)*128;
    const float* zi = g_dfti + (size_t)(b*Cq+c)*128;
    float Fr[4]={0,0,0,0}, Fi[4]={0,0,0,0};
    for (int h = 0; h < 32; h++){
        int ix = (kh*h)&31; float ch = tc[ix], sh = ts[ix];
#pragma unroll
        for (int kw = 0; kw < 4; kw++){
            float yr = zr[h*4+kw], yi = zi[h*4+kw];
            Fr[kw] += yr*ch + yi*sh;
            Fi[kw] += yi*ch - yr*sh;
        }
    }
#pragma unroll
    for (int kw = 0; kw < 4; kw++){
        size_t o = ((size_t)((mh*4+kw)*Bq + b))*Cq + c;
        g_xfr[o] = Fr[kw]; g_xfi[o] = Fi[kw];
    }
}

__global__ __launch_bounds__(256) void k_mix(int conv){
    int mode = blockIdx.x, oc0 = blockIdx.y*128;
    __shared__ float2 sX[16][64];
    int t = threadIdx.x, oc = oc0 + (t & 127), half = t >> 7;
    const float* wr = g_wpr[conv]; const float* wi = g_wpi[conv];
    float accr[8], acci[8];
#pragma unroll
    for (int bb = 0; bb < 8; bb++){ accr[bb]=0.f; acci[bb]=0.f; }
    for (int ic0 = 0; ic0 < Cq; ic0 += 64){
        __syncthreads();
#pragma unroll
        for (int r = 0; r < 4; r++){
            int e = t + 256*r; int bb = e>>6, ii = e&63;
            size_t xi = ((size_t)(mode*Bq+bb))*Cq + ic0 + ii;
            sX[bb][ii] = make_float2(g_xfr[xi], g_xfi[xi]);
        }
        __syncthreads();
        const float* wrp = wr + ((size_t)mode*Cq + ic0)*Cq + oc;
        const float* wip = wi + ((size_t)mode*Cq + ic0)*Cq + oc;
#pragma unroll 4
        for (int i = 0; i < 64; i++){
            float wrv = wrp[(size_t)i*Cq], wiv = wip[(size_t)i*Cq];
#pragma unroll
            for (int bb = 0; bb < 8; bb++){
                float2 xv = sX[half*8+bb][i];
                accr[bb] += xv.x*wrv - xv.y*wiv;
                acci[bb] += xv.x*wiv + xv.y*wrv;
            }
        }
    }
#pragma unroll
    for (int bb = 0; bb < 8; bb++){
        size_t o = ((size_t)((half*8+bb)*Cq + oc))*NMODE + mode;
        g_ofr[o] = accr[bb]; g_ofi[o] = acci[bb];
    }
}

__global__ __launch_bounds__(256) void k_idft_h(){
    __shared__ float tc[32], ts[32];
    if (threadIdx.x < 32){ float a = 6.283185307179586f*threadIdx.x/32.f; tc[threadIdx.x]=cosf(a); ts[threadIdx.x]=sinf(a); }
    __syncthreads();
    int gid = blockIdx.x*256 + threadIdx.x;
    int h = gid & 31, bc = gid >> 5;
    const float* Or = g_ofr + (size_t)bc*NMODE;
    const float* Oi = g_ofi + (size_t)bc*NMODE;
    float zr[4]={0,0,0,0}, zi[4]={0,0,0,0};
    for (int mh = 0; mh < 14; mh++){
        int kh = (mh < 7) ? mh : mh + 18;
        int ix = (kh*h)&31; float ch = tc[ix], sh = ts[ix];
#pragma unroll
        for (int kw = 0; kw < 4; kw++){
            float a = Or[mh*4+kw], bb = Oi[mh*4+kw];
            zr[kw] += a*ch - bb*sh;
            zi[kw] += a*sh + bb*ch;
        }
    }
    size_t o = (size_t)gid << 2;
#pragma unroll
    for (int kw = 0; kw < 4; kw++){ g_dftr[o+kw]=zr[kw]; g_dfti[o+kw]=zi[kw]; }
}

__global__ __launch_bounds__(256) void k_idft_w(int sel){
    __shared__ float tc[32], ts[32];
    if (threadIdx.x < 32){ float a = 6.283185307179586f*threadIdx.x/32.f; tc[threadIdx.x]=cosf(a); ts[threadIdx.x]=sinf(a); }
    __syncthreads();
    float* dst = sel ? g_cv : g_fimg;
    int gid = blockIdx.x*256 + threadIdx.x;
    int h = gid & 31, bc = gid >> 5;
    size_t zo = (size_t)gid << 2;
    float zr[4], zi[4];
#pragma unroll
    for (int kw = 0; kw < 4; kw++){ zr[kw]=g_dftr[zo+kw]; zi[kw]=g_dfti[zo+kw]; }
    float* orow = dst + ((size_t)bc << 10) + (h << 5);
    for (int w = 0; w < 32; w++){
        float acc = zr[0];
#pragma unroll
        for (int kw = 1; kw < 4; kw++){
            int ix = (kw*w)&31;
            acc += 2.f*(zr[kw]*tc[ix] - zi[kw]*ts[ix]);
        }
        orow[w] = acc * (1.f/1024.f);
    }
}

__global__ void k_cm2tm_split(const float* __restrict__ src){
    __shared__ float tile[32][33];
    int b = blockIdx.x, n0 = blockIdx.y*32, c0 = blockIdx.z*32;
    int tx = threadIdx.x, ty = threadIdx.y;
#pragma unroll
    for (int j = 0; j < 4; j++)
        tile[ty+j*8][tx] = src[((size_t)(b*Cq + c0+ty+j*8) << 10) + n0 + tx];
    __syncthreads();
#pragma unroll
    for (int j = 0; j < 4; j++){
        size_t idx = ((size_t)(b<<10) + n0+ty+j*8)*Cq + c0 + tx;
        split_write(g_ah, g_al, idx, tile[tx][ty+j*8]);
    }
}

__global__ void k_tm2cm(const float* __restrict__ src, float* __restrict__ dst, int stride, int off){
    __shared__ float tile[32][33];
    int b = blockIdx.x, n0 = blockIdx.y*32, c0 = blockIdx.z*32;
    int tx = threadIdx.x, ty = threadIdx.y;
#pragma unroll
    for (int j = 0; j < 4; j++)
        tile[ty+j*8][tx] = src[((size_t)(b<<10) + n0+ty+j*8)*stride + off + c0 + tx];
    __syncthreads();
#pragma unroll
    for (int j = 0; j < 4; j++)
        dst[((size_t)(b*Cq + c0+ty+j*8) << 10) + n0 + tx] = tile[tx][ty+j*8];
}

__global__ void k_final(float* __restrict__ dst){
    __shared__ float tile[32][33];
    int b = blockIdx.x, n0 = blockIdx.y*32, c0 = blockIdx.z*32;
    int tx = threadIdx.x, ty = threadIdx.y;
#pragma unroll
    for (int j = 0; j < 4; j++){
        size_t i = ((size_t)(b<<10) + n0+ty+j*8)*Cq + c0 + tx;
        tile[ty+j*8][tx] = g_tres[i] + g_uln[i];
    }
    __syncthreads();
#pragma unroll
    for (int j = 0; j < 4; j++)
        dst[((size_t)(b*Cq + c0+ty+j*8) << 10) + n0 + tx] = tile[tx][ty+j*8];
}

// ---- tensor-core GEMM: pre-split bf16 x3, 128x128x32, 512thr, 3-stage ----
__device__ __forceinline__ uint32_t s2u(const void* p){ return (uint32_t)__cvta_generic_to_shared(p); }
__device__ __forceinline__ void cp16(uint32_t d, const void* g){
    asm volatile("cp.async.ca.shared.global [%0],[%1],16;" :: "r"(d), "l"(g));
}
__device__ __forceinline__ void ldsm4(uint32_t& a0,uint32_t& a1,uint32_t& a2,uint32_t& a3,uint32_t ad){
    asm volatile("ldmatrix.sync.aligned.m8n8.x4.shared.b16 {%0,%1,%2,%3},[%4];"
        : "=r"(a0),"=r"(a1),"=r"(a2),"=r"(a3) : "r"(ad));
}
__device__ __forceinline__ void ldsm4t(uint32_t& a0,uint32_t& a1,uint32_t& a2,uint32_t& a3,uint32_t ad){
    asm volatile("ldmatrix.sync.aligned.m8n8.x4.trans.shared.b16 {%0,%1,%2,%3},[%4];"
        : "=r"(a0),"=r"(a1),"=r"(a2),"=r"(a3) : "r"(ad));
}
__device__ __forceinline__ void mma16816(float* d,const uint32_t* a,uint32_t b0,uint32_t b1){
    asm volatile("mma.sync.aligned.m16n8k16.row.col.f32.bf16.bf16.f32 "
        "{%0,%1,%2,%3},{%4,%5,%6,%7},{%8,%9},{%0,%1,%2,%3};"
        : "+f"(d[0]),"+f"(d[1]),"+f"(d[2]),"+f"(d[3])
        : "r"(a[0]),"r"(a[1]),"r"(a[2]),"r"(a[3]),"r"(b0),"r"(b1));
}

#define STG_A 5120
#define STG_B 4352
#define STG_ELEMS (2*STG_A + 2*STG_B)
#define NSTG 3
#define SM_BYTES (STG_ELEMS*NSTG*2)

__global__ __launch_bounds__(512) void k_gemm(const __nv_bfloat16* __restrict__ Agh, const __nv_bfloat16* __restrict__ Agl,
                                              const __nv_bfloat16* __restrict__ Bgh, const __nv_bfloat16* __restrict__ Bgl,
                                              const float* __restrict__ bias, const float* __restrict__ resid,
                                              float* __restrict__ C, int M, int N, int K){
    extern __shared__ __nv_bfloat16 sm[];
    int t = threadIdx.x, lane = t & 31, wid = t >> 5;
    int wr = wid >> 2, wc = wid & 3;           // 4x4 warp grid, 32x32 warp tile
    int m0 = blockIdx.y*128, n0 = blockIdx.x*128;
    float acc[2][4][4];
#pragma unroll
    for (int mi=0;mi<2;mi++)
#pragma unroll
        for (int ni=0;ni<4;ni++)
#pragma unroll
            for (int j=0;j<4;j++) acc[mi][ni][j]=0.f;

    int a_row = t>>2, a_ch = t&3;              // 128 rows x 4 chunks
    int b_row = t>>4, b_ch = t&15;             // 32 rows x 16 chunks
    int nk = K >> 5;

    auto LOAD = [&](int kt){
        __nv_bfloat16* base = sm + (kt%NSTG)*STG_ELEMS;
        const __nv_bfloat16* gah = Agh + (size_t)(m0+a_row)*K + kt*32 + a_ch*8;
        const __nv_bfloat16* gal = Agl + (size_t)(m0+a_row)*K + kt*32 + a_ch*8;
        cp16(s2u(base + a_row*40 + a_ch*8), gah);
        cp16(s2u(base + STG_A + a_row*40 + a_ch*8), gal);
        const __nv_bfloat16* gbh = Bgh + (size_t)(kt*32+b_row)*N + n0 + b_ch*8;
        const __nv_bfloat16* gbl = Bgl + (size_t)(kt*32+b_row)*N + n0 + b_ch*8;
        cp16(s2u(base + 2*STG_A + b_row*136 + b_ch*8), gbh);
        cp16(s2u(base + 2*STG_A + STG_B + b_row*136 + b_ch*8), gbl);
        asm volatile("cp.async.commit_group;");
    };

    LOAD(0);
    if (nk > 1) LOAD(1);
    for (int kt = 0; kt < nk; kt++){
        if (kt+1 < nk) asm volatile("cp.async.wait_group 1;" ::: "memory");
        else           asm volatile("cp.async.wait_group 0;" ::: "memory");
        __syncthreads();
        if (kt+2 < nk) LOAD(kt+2);   // writes slot (kt+2)%3 == (kt-1)%3: consumed, all threads past barrier
        const __nv_bfloat16* base = sm + (kt%NSTG)*STG_ELEMS;
        const __nv_bfloat16* sAh = base;
        const __nv_bfloat16* sAl = base + STG_A;
        const __nv_bfloat16* sBh = base + 2*STG_A;
        const __nv_bfloat16* sBl = base + 2*STG_A + STG_B;
#pragma unroll
        for (int kh = 0; kh < 2; kh++){
            uint32_t ah[2][4], al[2][4];
            int arow = wr*32 + (lane&15);
            int acol = (lane>>4)*8 + kh*16;
#pragma unroll
            for (int mi=0;mi<2;mi++){
                ldsm4(ah[mi][0],ah[mi][1],ah[mi][2],ah[mi][3], s2u(sAh + (arow+mi*16)*40 + acol));
                ldsm4(al[mi][0],al[mi][1],al[mi][2],al[mi][3], s2u(sAl + (arow+mi*16)*40 + acol));
            }
            int brow = kh*16 + (lane&15);
#pragma unroll
            for (int ni=0;ni<2;ni++){
                int bcol = wc*32 + ni*16 + (lane>>4)*8;
                uint32_t bh[4], bl[4];
                ldsm4t(bh[0],bh[1],bh[2],bh[3], s2u(sBh + brow*136 + bcol));
                ldsm4t(bl[0],bl[1],bl[2],bl[3], s2u(sBl + brow*136 + bcol));
#pragma unroll
                for (int mi=0;mi<2;mi++){
                    mma16816(acc[mi][ni*2],   ah[mi], bh[0],bh[1]);
                    mma16816(acc[mi][ni*2+1], ah[mi], bh[2],bh[3]);
                    mma16816(acc[mi][ni*2],   ah[mi], bl[0],bl[1]);
                    mma16816(acc[mi][ni*2+1], ah[mi], bl[2],bl[3]);
                    mma16816(acc[mi][ni*2],   al[mi], bh[0],bh[1]);
                    mma16816(acc[mi][ni*2+1], al[mi], bh[2],bh[3]);
                }
            }
        }
    }
#pragma unroll
    for (int mi=0;mi<2;mi++)
#pragma unroll
        for (int ni=0;ni<4;ni++){
            int col = n0 + wc*32 + ni*8 + (lane&3)*2;
            float bz0 = bias ? bias[col] : 0.f;
            float bz1 = bias ? bias[col+1] : 0.f;
#pragma unroll
            for (int hf=0; hf<2; hf++){
                size_t row = (size_t)m0 + wr*32 + mi*16 + (lane>>2) + hf*8;
                float v0 = acc[mi][ni][hf*2+0] + bz0;
                float v1 = acc[mi][ni][hf*2+1] + bz1;
                if (resid){ v0 += resid[row*N+col]; v1 += resid[row*N+col+1]; }
                C[row*N+col] = v0; C[row*N+col+1] = v1;
            }
        }
}

__global__ void k_ksoft(){
    int b = blockIdx.x, c = blockIdx.y*32 + threadIdx.x, ny = threadIdx.y;
    float m = -1e30f, s = 0.f;
    for (int n = ny; n < Nq; n += 8){
        float v = g_qkv[((size_t)(b<<10)+n)*2304 + 768 + c];
        float nm = fmaxf(m, v);
        s = s*expf(m-nm) + expf(v-nm);
        m = nm;
    }
    __shared__ float sm[8][32], ss[8][32];
    sm[ny][threadIdx.x] = m; ss[ny][threadIdx.x] = s;
    __syncthreads();
    if (ny == 0){
        float M = sm[0][threadIdx.x], S = ss[0][threadIdx.x];
#pragma unroll
        for (int r = 1; r < 8; r++){
            float m2 = sm[r][threadIdx.x], s2 = ss[r][threadIdx.x];
            float nm = fmaxf(M, m2);
            S = S*expf(M-nm) + s2*expf(m2-nm);
            M = nm;
        }
        g_kmax[b*Cq+c] = M;
        g_krcp[b*Cq+c] = 1.f/S;
    }
}

__global__ __launch_bounds__(256) void k_kv(){
    int b = blockIdx.x, h = blockIdx.y;
    __shared__ float ks[32][96], vs[32][96];
    int t = threadIdx.x;
    int i0 = (t>>4)*6, j0 = (t&15)*6;
    float acc[6][6];
#pragma unroll
    for (int i = 0; i < 6; i++)
#pragma unroll
        for (int j = 0; j < 6; j++) acc[i][j] = 0.f;
    int ck = 768 + h*Chq, cvx = 1536 + h*Chq, cb = b*Cq + h*Chq;
    for (int n0 = 0; n0 < Nq; n0 += 32){
        __syncthreads();
#pragma unroll
        for (int r = 0; r < 12; r++){
            int e = t + 256*r;
            int nn = e/96, j = e%96;
            size_t ro = ((size_t)(b<<10) + n0 + nn)*2304;
            ks[nn][j] = expf(g_qkv[ro+ck+j] - g_kmax[cb+j]) * g_krcp[cb+j];
            vs[nn][j] = g_qkv[ro+cvx+j];
        }
        __syncthreads();
#pragma unroll 4
        for (int nn = 0; nn < 32; nn++){
            float a[6], bb[6];
#pragma unroll
            for (int x = 0; x < 6; x++){ a[x]=ks[nn][i0+x]; bb[x]=vs[nn][j0+x]; }
#pragma unroll
            for (int i = 0; i < 6; i++)
#pragma unroll
                for (int j = 0; j < 6; j++) acc[i][j] += a[i]*bb[j];
        }
    }
#pragma unroll
    for (int i = 0; i < 6; i++)
#pragma unroll
        for (int j = 0; j < 6; j++)
            g_kv[((size_t)((b*Hh+h)*Chq) + i0+i)*Chq + j0+j] = acc[i][j];
}

__global__ __launch_bounds__(256) void k_fa(){
    int b = blockIdx.x, h = blockIdx.y, n0 = blockIdx.z*32;
    __shared__ float kvs[96*96];
    __shared__ float qs[96*32];
    int t = threadIdx.x;
    const float* kvsrc = g_kv + (size_t)(b*Hh+h)*Chq*Chq;
#pragma unroll
    for (int r = 0; r < 36; r++) kvs[t+256*r] = kvsrc[t+256*r];
#pragma unroll
    for (int r = 0; r < 12; r++){
        int e = t + 256*r;
        int j = e >> 5, n = e & 31;
        qs[e] = g_qkv[((size_t)(b<<10)+n0+n)*2304 + h*Chq + j];
    }
    __syncthreads();
    int n = t & 31, i0 = (t>>5)*12;
    float acc[12];
#pragma unroll
    for (int i = 0; i < 12; i++) acc[i] = 0.f;
    for (int j = 0; j < 96; j++){
        float qv = qs[j*32 + n];
        const float* kr = &kvs[j*96 + i0];
#pragma unroll
        for (int i = 0; i < 12; i++) acc[i] += qv * kr[i];
    }
    const float scale = 0.10206207261596577f;
    float val[12];
#pragma unroll
    for (int i = 0; i < 12; i++){
        float cvv = g_cv[((size_t)(b*Cq + h*Chq + i0+i) << 10) + n0 + n];
        float sg = 1.f/(1.f + expf(-cvv));
        val[i] = scale*acc[i] + qs[(i0+i)*32 + n]*sg;
    }
    __syncthreads();
#pragma unroll
    for (int i = 0; i < 12; i++) qs[n*96 + i0+i] = val[i];
    __syncthreads();
#pragma unroll
    for (int r = 0; r < 12; r++){
        int e = t + 256*r;
        int nn = e/96, c = e%96;
        size_t idx = ((size_t)(b<<10)+n0+nn)*Cq + h*Chq + c;
        split_write(g_ah, g_al, idx, qs[e]);
    }
}

template<int L, bool GELU, bool SPLIT>
__global__ __launch_bounds__(256) void k_lnrow(const float* __restrict__ in, const float* __restrict__ g,
                                               const float* __restrict__ be, float* __restrict__ out){
    int row = blockIdx.x, t = threadIdx.x;
    const float* p = in + (size_t)row*L;
    float v[L/256];
    float s = 0.f, s2 = 0.f;
#pragma unroll
    for (int i = 0; i < L/256; i++){ v[i] = p[t + i*256]; s += v[i]; s2 += v[i]*v[i]; }
    __shared__ float ra[32], rb[32];
#pragma unroll
    for (int o = 16; o; o >>= 1){ s += __shfl_down_sync(~0u, s, o); s2 += __shfl_down_sync(~0u, s2, o); }
    if (!(t & 31)){ ra[t>>5] = s; rb[t>>5] = s2; }
    __syncthreads();
    if (t < 8){
        s = ra[t]; s2 = rb[t];
#pragma unroll
        for (int o = 4; o; o >>= 1){ s += __shfl_down_sync(0xff, s, o); s2 += __shfl_down_sync(0xff, s2, o); }
        if (!t){ ra[0] = s; rb[0] = s2; }
    }
    __syncthreads();
    float m = ra[0]*(1.f/L);
    float r = rsqrtf(rb[0]*(1.f/L) - m*m + 1e-5f);
    float* q = out + (size_t)row*L;
#pragma unroll
    for (int i = 0; i < L/256; i++){
        int c = t + i*256;
        float x = (v[i]-m)*r*g[c] + be[c];
        if (GELU) x = 0.5f*x*(1.f + erff(x*0.7071067811865476f));
        if (SPLIT) split_write(g_ah, g_al, (size_t)row*L + c, x);
        else q[c] = x;
    }
}

__global__ __launch_bounds__(256) void k_dw(const float* __restrict__ in, const float* __restrict__ w,
                                            const float* __restrict__ bias){
    int c = blockIdx.x*256 + threadIdx.x;
    int h = blockIdx.y, b = blockIdx.z;
    float wv[9];
#pragma unroll
    for (int i = 0; i < 9; i++) wv[i] = w[(size_t)c*9 + i];
    float bb = bias[c];
    size_t base = ((size_t)b << 10)*HIDq + c;
    float p[3], q[3], r[3];
#pragma unroll
    for (int i = 0; i < 3; i++){
        int hh = h-1+i;
        p[i] = 0.f;
        q[i] = (hh >= 0 && hh < 32) ? in[base + (size_t)(hh*32)*HIDq] : 0.f;
        r[i] = (hh >= 0 && hh < 32) ? in[base + (size_t)(hh*32+1)*HIDq] : 0.f;
    }
    for (int w0 = 0; w0 < 32; w0++){
        float acc = bb;
#pragma unroll
        for (int i = 0; i < 3; i++) acc += p[i]*wv[i*3] + q[i]*wv[i*3+1] + r[i]*wv[i*3+2];
        split_write(g_ah, g_al, base + (size_t)(h*32+w0)*HIDq, acc);
#pragma unroll
        for (int i = 0; i < 3; i++){
            p[i] = q[i]; q[i] = r[i];
            int hh = h-1+i;
            r[i] = (w0+2 < 32 && hh >= 0 && hh < 32) ? in[base + (size_t)(hh*32+w0+2)*HIDq] : 0.f;
        }
    }
}

extern "C" void kernel_launch(void* const* d_in, const int* in_sizes, int n_in,
                              void* d_out, int out_size){
    static const int ord_dict[26] = {0,18,19,1,2,3,4,9,5,6,7,8,10,11,20,21,12,13,22,23,16,17,14,15,24,25};
    const float* I[26];
    bool sig = (in_sizes[1] == 768);
    for (int i = 0; i < 26; i++) I[i] = (const float*)d_in[sig ? i : ord_dict[i]];
    const float *x=I[0], *ln1g=I[1], *ln1b=I[2];
    const float *f1w1r=I[3], *f1w1i=I[4], *f1w2r=I[5], *f1w2i=I[6];
    const float *wqkv=I[7];
    const float *f2w1r=I[8], *f2w1i=I[9], *f2w2r=I[10], *f2w2i=I[11];
    const float *wproj=I[12], *bproj=I[13], *ln2g=I[14], *ln2b=I[15];
    const float *fc1w=I[16], *fc1b=I[17], *mln1g=I[18], *mln1b=I[19];
    const float *dww=I[20], *dwb=I[21], *fc2w=I[22], *fc2b=I[23];
    const float *mln2g=I[24], *mln2b=I[25];
    float* out = (float*)d_out;

    void *p;
    cudaGetSymbolAddress(&p, g_qkv ); float* qkv  = (float*)p;
    cudaGetSymbolAddress(&p, g_tln ); float* tln  = (float*)p;
    cudaGetSymbolAddress(&p, g_tres); float* tres = (float*)p;
    cudaGetSymbolAddress(&p, g_uln ); float* uln  = (float*)p;
    cudaGetSymbolAddress(&p, g_u1  ); float* u1   = (float*)p;
    cudaGetSymbolAddress(&p, g_u1g ); float* u1g  = (float*)p;
    cudaGetSymbolAddress(&p, g_u2  ); float* u2   = (float*)p;
    cudaGetSymbolAddress(&p, g_fimg); float* fimg = (float*)p;
    cudaGetSymbolAddress(&p, g_vimg); float* vimg = (float*)p;
    cudaGetSymbolAddress(&p, g_ah); __nv_bfloat16* ah = (__nv_bfloat16*)p;
    cudaGetSymbolAddress(&p, g_al); __nv_bfloat16* al = (__nv_bfloat16*)p;
    cudaGetSymbolAddress(&p, g_wh); __nv_bfloat16* wh = (__nv_bfloat16*)p;
    cudaGetSymbolAddress(&p, g_wl); __nv_bfloat16* wl = (__nv_bfloat16*)p;

    cudaFuncSetAttribute(k_gemm, cudaFuncAttributeMaxDynamicSharedMemorySize, SM_BYTES);

    dim3 rp(768, 3); dim3 t32x8(32, 8); dim3 tr(16, 32, 24);
    k_repack<<<rp,256>>>(f1w1r,0,0,0); k_repack<<<rp,256>>>(f1w1i,0,1,0);
    k_repack<<<rp,256>>>(f1w2r,0,0,7); k_repack<<<rp,256>>>(f1w2i,0,1,7);
    k_repack<<<rp,256>>>(f2w1r,1,0,0); k_repack<<<rp,256>>>(f2w1i,1,1,0);
    k_repack<<<rp,256>>>(f2w2r,1,0,7); k_repack<<<rp,256>>>(f2w2i,1,1,7);

    k_ln1_stats<<<dim3(16,4),256>>>(x);
    k_lnT<<<tr,t32x8>>>(x, ln1g, ln1b);

    k_dft_w<<<1536,256>>>(x, ln1g, ln1b, 1);
    k_dft_h<<<672,256>>>();
    k_mix<<<dim3(56,6),256>>>(0);
    k_idft_h<<<1536,256>>>();
    k_idft_w<<<1536,256>>>(0);
    k_cm2tm_split<<<tr,t32x8>>>(fimg);

    k_wsplit<<<6912,256>>>(wqkv, (size_t)768*2304);
    k_gemm<<<dim3(18,128),512,SM_BYTES>>>(ah, al, wh, wl, nullptr, nullptr, qkv, NROWS, 2304, 768);
    k_ksoft<<<dim3(16,24),t32x8>>>();
    k_kv<<<dim3(16,8),256>>>();

    k_tm2cm<<<tr,t32x8>>>(qkv, vimg, 2304, 1536);
    k_dft_w<<<1536,256>>>(nullptr, nullptr, nullptr, 0);
    k_dft_h<<<672,256>>>();
    k_mix<<<dim3(56,6),256>>>(1);
    k_idft_h<<<1536,256>>>();
    k_idft_w<<<1536,256>>>(1);

    k_fa<<<dim3(16,8,32),256>>>();
    k_wsplit<<<2304,256>>>(wproj, (size_t)768*768);
    k_gemm<<<dim3(6,128),512,SM_BYTES>>>(ah, al, wh, wl, bproj, tln, tres, NROWS, 768, 768);

    k_lnrow<768,false,true><<<NROWS,256>>>(tres, ln2g, ln2b, nullptr);
    k_wsplit<<<9216,256>>>(fc1w, (size_t)768*3072);
    k_gemm<<<dim3(24,128),512,SM_BYTES>>>(ah, al, wh, wl, fc1b, nullptr, u1, NROWS, 3072, 768);
    k_lnrow<3072,true,false><<<NROWS,256>>>(u1, mln1g, mln1b, u1g);
    k_dw<<<dim3(12,32,16),256>>>(u1g, dww, dwb);
    k_wsplit<<<9216,256>>>(fc2w, (size_t)3072*768);
    k_gemm<<<dim3(6,128),512,SM_BYTES>>>(ah, al, wh, wl, fc2b, nullptr, u2, NROWS, 768, 3072);
    k_lnrow<768,false,false><<<NROWS,256>>>(u2, mln2g, mln2b, uln);
    k_final<<<tr,t32x8>>>(out);
    (void)n_in; (void)out_size;
}

// round 16
// speedup vs baseline: 1.2372x; 1.2372x over previous
#include <cuda_runtime.h>
#include <cuda_bf16.h>
#include <cuda_fp16.h>
#include <math.h>
#include <stdint.h>
#include <stddef.h>

#define Bq 16
#define Cq 768
#define Nq 1024
#define Hh 8
#define Chq 96
#define HIDq 3072
#define NMODE 56
#define NROWS (Bq*Nq)
#define WPSZ ((size_t)NMODE*Cq*Cq)

__device__ float g_mean[NROWS];
__device__ float g_rstd[NROWS];
__device__ float g_tln [(size_t)NROWS*Cq];
__device__ float g_dftr[(size_t)Bq*Cq*32*4];
__device__ float g_dfti[(size_t)Bq*Cq*32*4];
__device__ float g_xfr [(size_t)NMODE*Bq*Cq];
__device__ float g_xfi [(size_t)NMODE*Bq*Cq];
__device__ float g_ofr [(size_t)Bq*Cq*NMODE];
__device__ float g_ofi [(size_t)Bq*Cq*NMODE];
__device__ float g_fimg[(size_t)Bq*Cq*Nq];
__device__ float g_qkv [(size_t)NROWS*3*Cq];
__device__ float g_kmax[Bq*Cq];
__device__ float g_krcp[Bq*Cq];
__device__ float g_kv  [(size_t)Bq*Hh*Chq*Chq];
__device__ float g_vimg[(size_t)Bq*Cq*Nq];
__device__ float g_cv  [(size_t)Bq*Cq*Nq];
__device__ float g_tres[(size_t)NROWS*Cq];
__device__ float g_uln [(size_t)NROWS*Cq];
__device__ float g_u1  [(size_t)NROWS*HIDq];
__device__ float g_u1g [(size_t)NROWS*HIDq];
__device__ float g_u2  [(size_t)NROWS*Cq];
__device__ float g_wpr [2][WPSZ];
__device__ float g_wpi [2][WPSZ];
// fp16 operands: activations quantized (single), weights split hi/lo
__device__ __half g_ah[(size_t)NROWS*HIDq];
__device__ __half g_wh[(size_t)HIDq*Cq];
__device__ __half g_wl[(size_t)HIDq*Cq];

__device__ __forceinline__ void act_write(size_t idx, float x){
    g_ah[idx] = __float2half_rn(x);
}
__device__ __forceinline__ void wsplit_write(size_t idx, float x){
    __half h = __float2half_rn(x);
    g_wh[idx] = h;
    g_wl[idx] = __float2half_rn(x - __half2float(h));
}

__global__ __launch_bounds__(256) void k_repack(const float* __restrict__ w, int conv, int ri, int mh0){
    float* dst = ri ? g_wpi[conv] : g_wpr[conv];
    int ic = blockIdx.x, oc = blockIdx.y*256 + threadIdx.x;
    const float* s = w + ((size_t)ic*Cq + oc)*28;
    float v[28];
#pragma unroll
    for (int k = 0; k < 28; k++) v[k] = s[k];
#pragma unroll
    for (int m1 = 0; m1 < 7; m1++)
#pragma unroll
        for (int kw = 0; kw < 4; kw++)
            dst[((size_t)((mh0+m1)*4+kw)*Cq + ic)*Cq + oc] = v[m1*4+kw];
}

__global__ __launch_bounds__(256) void k_wsplit(const float* __restrict__ w, size_t n){
    size_t i = (size_t)blockIdx.x*256 + threadIdx.x;
    if (i < n) wsplit_write(i, w[i]);
}

__global__ __launch_bounds__(256) void k_ln1_stats(const float* __restrict__ x){
    int b = blockIdx.x, n = blockIdx.y*256 + threadIdx.x;
    const float* p = x + ((size_t)b*Cq << 10) + n;
    float s = 0.f, s2 = 0.f;
#pragma unroll 4
    for (int c = 0; c < Cq; c++){ float v = p[(size_t)c << 10]; s += v; s2 += v*v; }
    float m = s*(1.f/Cq);
    g_mean[(b<<10)+n] = m;
    g_rstd[(b<<10)+n] = rsqrtf(s2*(1.f/Cq) - m*m + 1e-5f);
}

__global__ void k_lnT(const float* __restrict__ x, const float* __restrict__ g, const float* __restrict__ be){
    __shared__ float tile[32][33];
    int b = blockIdx.x, n0 = blockIdx.y*32, c0 = blockIdx.z*32;
    int tx = threadIdx.x, ty = threadIdx.y;
#pragma unroll
    for (int j = 0; j < 4; j++)
        tile[ty+j*8][tx] = x[((size_t)(b*Cq + c0+ty+j*8) << 10) + n0 + tx];
    __syncthreads();
#pragma unroll
    for (int j = 0; j < 4; j++){
        int n = n0+ty+j*8, c = c0+tx;
        float m = g_mean[(b<<10)+n], r = g_rstd[(b<<10)+n];
        g_tln[((size_t)(b<<10)+n)*Cq + c] = (tile[tx][ty+j*8]-m)*r*g[c] + be[c];
    }
}

__global__ __launch_bounds__(256) void k_dft_w(const float* __restrict__ xext,
                                               const float* __restrict__ lg, const float* __restrict__ lb,
                                               int do_ln){
    __shared__ float tc[32], ts[32];
    if (threadIdx.x < 32){ float a = 6.283185307179586f*threadIdx.x/32.f; tc[threadIdx.x]=cosf(a); ts[threadIdx.x]=sinf(a); }
    __syncthreads();
    int gid = blockIdx.x*256 + threadIdx.x;
    int h = gid & 31, bc = gid >> 5;
    int c = bc % Cq, b = bc / Cq;
    const float* src = do_ln ? xext : g_vimg;
    const float* row = src + ((size_t)bc << 10) + (h << 5);
    float ar[4] = {0,0,0,0}, ai[4] = {0,0,0,0};
    float gc = do_ln ? lg[c] : 0.f, bcv = do_ln ? lb[c] : 0.f;
    int nb = (b<<10) + (h<<5);
    for (int w = 0; w < 32; w++){
        float v = row[w];
        if (do_ln) v = (v - g_mean[nb+w])*g_rstd[nb+w]*gc + bcv;
        ar[0] += v;
#pragma unroll
        for (int kw = 1; kw < 4; kw++){
            int ix = (kw*w)&31;
            ar[kw] += v*tc[ix]; ai[kw] -= v*ts[ix];
        }
    }
    size_t o = (size_t)gid << 2;
#pragma unroll
    for (int kw = 0; kw < 4; kw++){ g_dftr[o+kw]=ar[kw]; g_dfti[o+kw]=ai[kw]; }
}

__global__ __launch_bounds__(256) void k_dft_h(){
    __shared__ float tc[32], ts[32];
    if (threadIdx.x < 32){ float a = 6.283185307179586f*threadIdx.x/32.f; tc[threadIdx.x]=cosf(a); ts[threadIdx.x]=sinf(a); }
    __syncthreads();
    int gid = blockIdx.x*256 + threadIdx.x;
    int c = gid % Cq, mh = (gid/Cq) % 14, b = gid/(Cq*14);
    int kh = (mh < 7) ? mh : mh + 18;
    const float* zr = g_dftr + (size_t)(b*Cq+c)*128;
    const float* zi = g_dfti + (size_t)(b*Cq+c)*128;
    float Fr[4]={0,0,0,0}, Fi[4]={0,0,0,0};
    for (int h = 0; h < 32; h++){
        int ix = (kh*h)&31; float ch = tc[ix], sh = ts[ix];
#pragma unroll
        for (int kw = 0; kw < 4; kw++){
            float yr = zr[h*4+kw], yi = zi[h*4+kw];
            Fr[kw] += yr*ch + yi*sh;
            Fi[kw] += yi*ch - yr*sh;
        }
    }
#pragma unroll
    for (int kw = 0; kw < 4; kw++){
        size_t o = ((size_t)((mh*4+kw)*Bq + b))*Cq + c;
        g_xfr[o] = Fr[kw]; g_xfi[o] = Fi[kw];
    }
}

__global__ __launch_bounds__(256) void k_mix(int conv){
    int mode = blockIdx.x, oc0 = blockIdx.y*128;
    __shared__ float2 sX[16][64];
    int t = threadIdx.x, oc = oc0 + (t & 127), half = t >> 7;
    const float* wr = g_wpr[conv]; const float* wi = g_wpi[conv];
    float accr[8], acci[8];
#pragma unroll
    for (int bb = 0; bb < 8; bb++){ accr[bb]=0.f; acci[bb]=0.f; }
    for (int ic0 = 0; ic0 < Cq; ic0 += 64){
        __syncthreads();
#pragma unroll
        for (int r = 0; r < 4; r++){
            int e = t + 256*r; int bb = e>>6, ii = e&63;
            size_t xi = ((size_t)(mode*Bq+bb))*Cq + ic0 + ii;
            sX[bb][ii] = make_float2(g_xfr[xi], g_xfi[xi]);
        }
        __syncthreads();
        const float* wrp = wr + ((size_t)mode*Cq + ic0)*Cq + oc;
        const float* wip = wi + ((size_t)mode*Cq + ic0)*Cq + oc;
#pragma unroll 4
        for (int i = 0; i < 64; i++){
            float wrv = wrp[(size_t)i*Cq], wiv = wip[(size_t)i*Cq];
#pragma unroll
            for (int bb = 0; bb < 8; bb++){
                float2 xv = sX[half*8+bb][i];
                accr[bb] += xv.x*wrv - xv.y*wiv;
                acci[bb] += xv.x*wiv + xv.y*wrv;
            }
        }
    }
#pragma unroll
    for (int bb = 0; bb < 8; bb++){
        size_t o = ((size_t)((half*8+bb)*Cq + oc))*NMODE + mode;
        g_ofr[o] = accr[bb]; g_ofi[o] = acci[bb];
    }
}

__global__ __launch_bounds__(256) void k_idft_h(){
    __shared__ float tc[32], ts[32];
    if (threadIdx.x < 32){ float a = 6.283185307179586f*threadIdx.x/32.f; tc[threadIdx.x]=cosf(a); ts[threadIdx.x]=sinf(a); }
    __syncthreads();
    int gid = blockIdx.x*256 + threadIdx.x;
    int h = gid & 31, bc = gid >> 5;
    const float* Or = g_ofr + (size_t)bc*NMODE;
    const float* Oi = g_ofi + (size_t)bc*NMODE;
    float zr[4]={0,0,0,0}, zi[4]={0,0,0,0};
    for (int mh = 0; mh < 14; mh++){
        int kh = (mh < 7) ? mh : mh + 18;
        int ix = (kh*h)&31; float ch = tc[ix], sh = ts[ix];
#pragma unroll
        for (int kw = 0; kw < 4; kw++){
            float a = Or[mh*4+kw], bb = Oi[mh*4+kw];
            zr[kw] += a*ch - bb*sh;
            zi[kw] += a*sh + bb*ch;
        }
    }
    size_t o = (size_t)gid << 2;
#pragma unroll
    for (int kw = 0; kw < 4; kw++){ g_dftr[o+kw]=zr[kw]; g_dfti[o+kw]=zi[kw]; }
}

__global__ __launch_bounds__(256) void k_idft_w(int sel){
    __shared__ float tc[32], ts[32];
    if (threadIdx.x < 32){ float a = 6.283185307179586f*threadIdx.x/32.f; tc[threadIdx.x]=cosf(a); ts[threadIdx.x]=sinf(a); }
    __syncthreads();
    float* dst = sel ? g_cv : g_fimg;
    int gid = blockIdx.x*256 + threadIdx.x;
    int h = gid & 31, bc = gid >> 5;
    size_t zo = (size_t)gid << 2;
    float zr[4], zi[4];
#pragma unroll
    for (int kw = 0; kw < 4; kw++){ zr[kw]=g_dftr[zo+kw]; zi[kw]=g_dfti[zo+kw]; }
    float* orow = dst + ((size_t)bc << 10) + (h << 5);
    for (int w = 0; w < 32; w++){
        float acc = zr[0];
#pragma unroll
        for (int kw = 1; kw < 4; kw++){
            int ix = (kw*w)&31;
            acc += 2.f*(zr[kw]*tc[ix] - zi[kw]*ts[ix]);
        }
        orow[w] = acc * (1.f/1024.f);
    }
}

__global__ void k_cm2tm_split(const float* __restrict__ src){
    __shared__ float tile[32][33];
    int b = blockIdx.x, n0 = blockIdx.y*32, c0 = blockIdx.z*32;
    int tx = threadIdx.x, ty = threadIdx.y;
#pragma unroll
    for (int j = 0; j < 4; j++)
        tile[ty+j*8][tx] = src[((size_t)(b*Cq + c0+ty+j*8) << 10) + n0 + tx];
    __syncthreads();
#pragma unroll
    for (int j = 0; j < 4; j++){
        size_t idx = ((size_t)(b<<10) + n0+ty+j*8)*Cq + c0 + tx;
        act_write(idx, tile[tx][ty+j*8]);
    }
}

__global__ void k_tm2cm(const float* __restrict__ src, float* __restrict__ dst, int stride, int off){
    __shared__ float tile[32][33];
    int b = blockIdx.x, n0 = blockIdx.y*32, c0 = blockIdx.z*32;
    int tx = threadIdx.x, ty = threadIdx.y;
#pragma unroll
    for (int j = 0; j < 4; j++)
        tile[ty+j*8][tx] = src[((size_t)(b<<10) + n0+ty+j*8)*stride + off + c0 + tx];
    __syncthreads();
#pragma unroll
    for (int j = 0; j < 4; j++)
        dst[((size_t)(b*Cq + c0+ty+j*8) << 10) + n0 + tx] = tile[tx][ty+j*8];
}

__global__ void k_final(float* __restrict__ dst){
    __shared__ float tile[32][33];
    int b = blockIdx.x, n0 = blockIdx.y*32, c0 = blockIdx.z*32;
    int tx = threadIdx.x, ty = threadIdx.y;
#pragma unroll
    for (int j = 0; j < 4; j++){
        size_t i = ((size_t)(b<<10) + n0+ty+j*8)*Cq + c0 + tx;
        tile[ty+j*8][tx] = g_tres[i] + g_uln[i];
    }
    __syncthreads();
#pragma unroll
    for (int j = 0; j < 4; j++)
        dst[((size_t)(b*Cq + c0+ty+j*8) << 10) + n0 + tx] = tile[tx][ty+j*8];
}

// ---- tensor-core GEMM: fp16 A (quantized) x fp16 weight hi/lo, 2 products
//      128x128x32 tile, 256 thr, 64x32 warp tile, cp.async 2-stage
__device__ __forceinline__ uint32_t s2u(const void* p){ return (uint32_t)__cvta_generic_to_shared(p); }
__device__ __forceinline__ void cp16(uint32_t d, const void* g){
    asm volatile("cp.async.ca.shared.global [%0],[%1],16;" :: "r"(d), "l"(g));
}
__device__ __forceinline__ void ldsm4(uint32_t& a0,uint32_t& a1,uint32_t& a2,uint32_t& a3,uint32_t ad){
    asm volatile("ldmatrix.sync.aligned.m8n8.x4.shared.b16 {%0,%1,%2,%3},[%4];"
        : "=r"(a0),"=r"(a1),"=r"(a2),"=r"(a3) : "r"(ad));
}
__device__ __forceinline__ void ldsm4t(uint32_t& a0,uint32_t& a1,uint32_t& a2,uint32_t& a3,uint32_t ad){
    asm volatile("ldmatrix.sync.aligned.m8n8.x4.trans.shared.b16 {%0,%1,%2,%3},[%4];"
        : "=r"(a0),"=r"(a1),"=r"(a2),"=r"(a3) : "r"(ad));
}
__device__ __forceinline__ void mma16816(float* d,const uint32_t* a,uint32_t b0,uint32_t b1){
    asm volatile("mma.sync.aligned.m16n8k16.row.col.f32.f16.f16.f32 "
        "{%0,%1,%2,%3},{%4,%5,%6,%7},{%8,%9},{%0,%1,%2,%3};"
        : "+f"(d[0]),"+f"(d[1]),"+f"(d[2]),"+f"(d[3])
        : "r"(a[0]),"r"(a[1]),"r"(a[2]),"r"(a[3]),"r"(b0),"r"(b1));
}

#define STG_A 5120
#define STG_B 4352
#define STG_ELEMS (STG_A + 2*STG_B)   /* 13824 halves per stage */
#define SM_BYTES (2*STG_ELEMS*2)      /* 55296 B */

__global__ __launch_bounds__(256) void k_gemm(const __half* __restrict__ Ag,
                                              const __half* __restrict__ Bgh, const __half* __restrict__ Bgl,
                                              const float* __restrict__ bias, const float* __restrict__ resid,
                                              float* __restrict__ C, int M, int N, int K){
    extern __shared__ __half sm[];
    int t = threadIdx.x, lane = t & 31, wid = t >> 5;
    int wr = wid >> 2, wc = wid & 3;
    int m0 = blockIdx.y*128, n0 = blockIdx.x*128;
    float acc[4][4][4];
#pragma unroll
    for (int mi=0;mi<4;mi++)
#pragma unroll
        for (int ni=0;ni<4;ni++)
#pragma unroll
            for (int j=0;j<4;j++) acc[mi][ni][j]=0.f;

    int a_row = t>>2, a_ch = t&3;
    int b_row = t>>4, b_ch = t&15;
    int nk = K >> 5;

    auto LOAD = [&](int kt, int st){
        __half* base = sm + st*STG_ELEMS;
#pragma unroll
        for (int i=0;i<2;i++){
            int row = a_row + i*64;
            cp16(s2u(base + row*40 + a_ch*8), Ag + (size_t)(m0+row)*K + kt*32 + a_ch*8);
        }
#pragma unroll
        for (int i=0;i<2;i++){
            int row = b_row + i*16;
            cp16(s2u(base + STG_A + row*136 + b_ch*8),
                 Bgh + (size_t)(kt*32+row)*N + n0 + b_ch*8);
            cp16(s2u(base + STG_A + STG_B + row*136 + b_ch*8),
                 Bgl + (size_t)(kt*32+row)*N + n0 + b_ch*8);
        }
        asm volatile("cp.async.commit_group;");
    };

    LOAD(0, 0);
    for (int kt = 0; kt < nk; kt++){
        if (kt+1 < nk){
            LOAD(kt+1, (kt+1)&1);
            asm volatile("cp.async.wait_group 1;" ::: "memory");
        } else {
            asm volatile("cp.async.wait_group 0;" ::: "memory");
        }
        __syncthreads();
        const __half* base = sm + (kt&1)*STG_ELEMS;
        const __half* sA  = base;
        const __half* sBh = base + STG_A;
        const __half* sBl = base + STG_A + STG_B;
#pragma unroll
        for (int kh = 0; kh < 2; kh++){
            uint32_t ah[4][4];
            int arow = wr*64 + (lane&15);
            int acol = (lane>>4)*8 + kh*16;
#pragma unroll
            for (int mi=0;mi<4;mi++)
                ldsm4(ah[mi][0],ah[mi][1],ah[mi][2],ah[mi][3], s2u(sA + (arow+mi*16)*40 + acol));
            int brow = kh*16 + (lane&15);
#pragma unroll
            for (int ni=0;ni<2;ni++){
                int bcol = wc*32 + ni*16 + (lane>>4)*8;
                uint32_t bh[4], bl[4];
                ldsm4t(bh[0],bh[1],bh[2],bh[3], s2u(sBh + brow*136 + bcol));
                ldsm4t(bl[0],bl[1],bl[2],bl[3], s2u(sBl + brow*136 + bcol));
#pragma unroll
                for (int mi=0;mi<4;mi++){
                    mma16816(acc[mi][ni*2],   ah[mi], bh[0],bh[1]);
                    mma16816(acc[mi][ni*2+1], ah[mi], bh[2],bh[3]);
                    mma16816(acc[mi][ni*2],   ah[mi], bl[0],bl[1]);
                    mma16816(acc[mi][ni*2+1], ah[mi], bl[2],bl[3]);
                }
            }
        }
        __syncthreads();
    }
#pragma unroll
    for (int mi=0;mi<4;mi++)
#pragma unroll
        for (int ni=0;ni<4;ni++){
            int col = n0 + wc*32 + ni*8 + (lane&3)*2;
            float bz0 = bias ? bias[col] : 0.f;
            float bz1 = bias ? bias[col+1] : 0.f;
#pragma unroll
            for (int hf=0; hf<2; hf++){
                size_t row = (size_t)m0 + wr*64 + mi*16 + (lane>>2) + hf*8;
                float v0 = acc[mi][ni][hf*2+0] + bz0;
                float v1 = acc[mi][ni][hf*2+1] + bz1;
                if (resid){ v0 += resid[row*N+col]; v1 += resid[row*N+col+1]; }
                C[row*N+col] = v0; C[row*N+col+1] = v1;
            }
        }
}

__global__ void k_ksoft(){
    int b = blockIdx.x, c = blockIdx.y*32 + threadIdx.x, ny = threadIdx.y;
    float m = -1e30f, s = 0.f;
    for (int n = ny; n < Nq; n += 8){
        float v = g_qkv[((size_t)(b<<10)+n)*2304 + 768 + c];
        float nm = fmaxf(m, v);
        s = s*expf(m-nm) + expf(v-nm);
        m = nm;
    }
    __shared__ float sm[8][32], ss[8][32];
    sm[ny][threadIdx.x] = m; ss[ny][threadIdx.x] = s;
    __syncthreads();
    if (ny == 0){
        float M = sm[0][threadIdx.x], S = ss[0][threadIdx.x];
#pragma unroll
        for (int r = 1; r < 8; r++){
            float m2 = sm[r][threadIdx.x], s2 = ss[r][threadIdx.x];
            float nm = fmaxf(M, m2);
            S = S*expf(M-nm) + s2*expf(m2-nm);
            M = nm;
        }
        g_kmax[b*Cq+c] = M;
        g_krcp[b*Cq+c] = 1.f/S;
    }
}

__global__ __launch_bounds__(256) void k_kv(){
    int b = blockIdx.x, h = blockIdx.y;
    __shared__ float ks[32][96], vs[32][96];
    int t = threadIdx.x;
    int i0 = (t>>4)*6, j0 = (t&15)*6;
    float acc[6][6];
#pragma unroll
    for (int i = 0; i < 6; i++)
#pragma unroll
        for (int j = 0; j < 6; j++) acc[i][j] = 0.f;
    int ck = 768 + h*Chq, cvx = 1536 + h*Chq, cb = b*Cq + h*Chq;
    for (int n0 = 0; n0 < Nq; n0 += 32){
        __syncthreads();
#pragma unroll
        for (int r = 0; r < 12; r++){
            int e = t + 256*r;
            int nn = e/96, j = e%96;
            size_t ro = ((size_t)(b<<10) + n0 + nn)*2304;
            ks[nn][j] = expf(g_qkv[ro+ck+j] - g_kmax[cb+j]) * g_krcp[cb+j];
            vs[nn][j] = g_qkv[ro+cvx+j];
        }
        __syncthreads();
#pragma unroll 4
        for (int nn = 0; nn < 32; nn++){
            float a[6], bb[6];
#pragma unroll
            for (int x = 0; x < 6; x++){ a[x]=ks[nn][i0+x]; bb[x]=vs[nn][j0+x]; }
#pragma unroll
            for (int i = 0; i < 6; i++)
#pragma unroll
                for (int j = 0; j < 6; j++) acc[i][j] += a[i]*bb[j];
        }
    }
#pragma unroll
    for (int i = 0; i < 6; i++)
#pragma unroll
        for (int j = 0; j < 6; j++)
            g_kv[((size_t)((b*Hh+h)*Chq) + i0+i)*Chq + j0+j] = acc[i][j];
}

__global__ __launch_bounds__(256) void k_fa(){
    int b = blockIdx.x, h = blockIdx.y, n0 = blockIdx.z*32;
    __shared__ float kvs[96*96];
    __shared__ float qs[96*32];
    int t = threadIdx.x;
    const float* kvsrc = g_kv + (size_t)(b*Hh+h)*Chq*Chq;
#pragma unroll
    for (int r = 0; r < 36; r++) kvs[t+256*r] = kvsrc[t+256*r];
#pragma unroll
    for (int r = 0; r < 12; r++){
        int e = t + 256*r;
        int j = e >> 5, n = e & 31;
        qs[e] = g_qkv[((size_t)(b<<10)+n0+n)*2304 + h*Chq + j];
    }
    __syncthreads();
    int n = t & 31, i0 = (t>>5)*12;
    float acc[12];
#pragma unroll
    for (int i = 0; i < 12; i++) acc[i] = 0.f;
    for (int j = 0; j < 96; j++){
        float qv = qs[j*32 + n];
        const float* kr = &kvs[j*96 + i0];
#pragma unroll
        for (int i = 0; i < 12; i++) acc[i] += qv * kr[i];
    }
    const float scale = 0.10206207261596577f;
    float val[12];
#pragma unroll
    for (int i = 0; i < 12; i++){
        float cvv = g_cv[((size_t)(b*Cq + h*Chq + i0+i) << 10) + n0 + n];
        float sg = 1.f/(1.f + expf(-cvv));
        val[i] = scale*acc[i] + qs[(i0+i)*32 + n]*sg;
    }
    __syncthreads();
#pragma unroll
    for (int i = 0; i < 12; i++) qs[n*96 + i0+i] = val[i];
    __syncthreads();
#pragma unroll
    for (int r = 0; r < 12; r++){
        int e = t + 256*r;
        int nn = e/96, c = e%96;
        size_t idx = ((size_t)(b<<10)+n0+nn)*Cq + h*Chq + c;
        act_write(idx, qs[e]);
    }
}

template<int L, bool GELU, bool SPLIT>
__global__ __launch_bounds__(256) void k_lnrow(const float* __restrict__ in, const float* __restrict__ g,
                                               const float* __restrict__ be, float* __restrict__ out){
    int row = blockIdx.x, t = threadIdx.x;
    const float* p = in + (size_t)row*L;
    float v[L/256];
    float s = 0.f, s2 = 0.f;
#pragma unroll
    for (int i = 0; i < L/256; i++){ v[i] = p[t + i*256]; s += v[i]; s2 += v[i]*v[i]; }
    __shared__ float ra[32], rb[32];
#pragma unroll
    for (int o = 16; o; o >>= 1){ s += __shfl_down_sync(~0u, s, o); s2 += __shfl_down_sync(~0u, s2, o); }
    if (!(t & 31)){ ra[t>>5] = s; rb[t>>5] = s2; }
    __syncthreads();
    if (t < 8){
        s = ra[t]; s2 = rb[t];
#pragma unroll
        for (int o = 4; o; o >>= 1){ s += __shfl_down_sync(0xff, s, o); s2 += __shfl_down_sync(0xff, s2, o); }
        if (!t){ ra[0] = s; rb[0] = s2; }
    }
    __syncthreads();
    float m = ra[0]*(1.f/L);
    float r = rsqrtf(rb[0]*(1.f/L) - m*m + 1e-5f);
    float* q = out + (size_t)row*L;
#pragma unroll
    for (int i = 0; i < L/256; i++){
        int c = t + i*256;
        float x = (v[i]-m)*r*g[c] + be[c];
        if (GELU) x = 0.5f*x*(1.f + erff(x*0.7071067811865476f));
        if (SPLIT) act_write((size_t)row*L + c, x);
        else q[c] = x;
    }
}

__global__ __launch_bounds__(256) void k_dw(const float* __restrict__ in, const float* __restrict__ w,
                                            const float* __restrict__ bias){
    int c = blockIdx.x*256 + threadIdx.x;
    int h = blockIdx.y, b = blockIdx.z;
    float wv[9];
#pragma unroll
    for (int i = 0; i < 9; i++) wv[i] = w[(size_t)c*9 + i];
    float bb = bias[c];
    size_t base = ((size_t)b << 10)*HIDq + c;
    float p[3], q[3], r[3];
#pragma unroll
    for (int i = 0; i < 3; i++){
        int hh = h-1+i;
        p[i] = 0.f;
        q[i] = (hh >= 0 && hh < 32) ? in[base + (size_t)(hh*32)*HIDq] : 0.f;
        r[i] = (hh >= 0 && hh < 32) ? in[base + (size_t)(hh*32+1)*HIDq] : 0.f;
    }
    for (int w0 = 0; w0 < 32; w0++){
        float acc = bb;
#pragma unroll
        for (int i = 0; i < 3; i++) acc += p[i]*wv[i*3] + q[i]*wv[i*3+1] + r[i]*wv[i*3+2];
        act_write(base + (size_t)(h*32+w0)*HIDq, acc);
#pragma unroll
        for (int i = 0; i < 3; i++){
            p[i] = q[i]; q[i] = r[i];
            int hh = h-1+i;
            r[i] = (w0+2 < 32 && hh >= 0 && hh < 32) ? in[base + (size_t)(hh*32+w0+2)*HIDq] : 0.f;
        }
    }
}

extern "C" void kernel_launch(void* const* d_in, const int* in_sizes, int n_in,
                              void* d_out, int out_size){
    static const int ord_dict[26] = {0,18,19,1,2,3,4,9,5,6,7,8,10,11,20,21,12,13,22,23,16,17,14,15,24,25};
    const float* I[26];
    bool sig = (in_sizes[1] == 768);
    for (int i = 0; i < 26; i++) I[i] = (const float*)d_in[sig ? i : ord_dict[i]];
    const float *x=I[0], *ln1g=I[1], *ln1b=I[2];
    const float *f1w1r=I[3], *f1w1i=I[4], *f1w2r=I[5], *f1w2i=I[6];
    const float *wqkv=I[7];
    const float *f2w1r=I[8], *f2w1i=I[9], *f2w2r=I[10], *f2w2i=I[11];
    const float *wproj=I[12], *bproj=I[13], *ln2g=I[14], *ln2b=I[15];
    const float *fc1w=I[16], *fc1b=I[17], *mln1g=I[18], *mln1b=I[19];
    const float *dww=I[20], *dwb=I[21], *fc2w=I[22], *fc2b=I[23];
    const float *mln2g=I[24], *mln2b=I[25];
    float* out = (float*)d_out;

    void *p;
    cudaGetSymbolAddress(&p, g_qkv ); float* qkv  = (float*)p;
    cudaGetSymbolAddress(&p, g_tln ); float* tln  = (float*)p;
    cudaGetSymbolAddress(&p, g_tres); float* tres = (float*)p;
    cudaGetSymbolAddress(&p, g_uln ); float* uln  = (float*)p;
    cudaGetSymbolAddress(&p, g_u1  ); float* u1   = (float*)p;
    cudaGetSymbolAddress(&p, g_u1g ); float* u1g  = (float*)p;
    cudaGetSymbolAddress(&p, g_u2  ); float* u2   = (float*)p;
    cudaGetSymbolAddress(&p, g_fimg); float* fimg = (float*)p;
    cudaGetSymbolAddress(&p, g_vimg); float* vimg = (float*)p;
    cudaGetSymbolAddress(&p, g_ah); __half* ah = (__half*)p;
    cudaGetSymbolAddress(&p, g_wh); __half* wh = (__half*)p;
    cudaGetSymbolAddress(&p, g_wl); __half* wl = (__half*)p;

    cudaFuncSetAttribute(k_gemm, cudaFuncAttributeMaxDynamicSharedMemorySize, SM_BYTES);

    dim3 rp(768, 3); dim3 t32x8(32, 8); dim3 tr(16, 32, 24);
    k_repack<<<rp,256>>>(f1w1r,0,0,0); k_repack<<<rp,256>>>(f1w1i,0,1,0);
    k_repack<<<rp,256>>>(f1w2r,0,0,7); k_repack<<<rp,256>>>(f1w2i,0,1,7);
    k_repack<<<rp,256>>>(f2w1r,1,0,0); k_repack<<<rp,256>>>(f2w1i,1,1,0);
    k_repack<<<rp,256>>>(f2w2r,1,0,7); k_repack<<<rp,256>>>(f2w2i,1,1,7);

    k_ln1_stats<<<dim3(16,4),256>>>(x);
    k_lnT<<<tr,t32x8>>>(x, ln1g, ln1b);

    k_dft_w<<<1536,256>>>(x, ln1g, ln1b, 1);
    k_dft_h<<<672,256>>>();
    k_mix<<<dim3(56,6),256>>>(0);
    k_idft_h<<<1536,256>>>();
    k_idft_w<<<1536,256>>>(0);
    k_cm2tm_split<<<tr,t32x8>>>(fimg);

    k_wsplit<<<6912,256>>>(wqkv, (size_t)768*2304);
    k_gemm<<<dim3(18,128),256,SM_BYTES>>>(ah, wh, wl, nullptr, nullptr, qkv, NROWS, 2304, 768);
    k_ksoft<<<dim3(16,24),t32x8>>>();
    k_kv<<<dim3(16,8),256>>>();

    k_tm2cm<<<tr,t32x8>>>(qkv, vimg, 2304, 1536);
    k_dft_w<<<1536,256>>>(nullptr, nullptr, nullptr, 0);
    k_dft_h<<<672,256>>>();
    k_mix<<<dim3(56,6),256>>>(1);
    k_idft_h<<<1536,256>>>();
    k_idft_w<<<1536,256>>>(1);

    k_fa<<<dim3(16,8,32),256>>>();
    k_wsplit<<<2304,256>>>(wproj, (size_t)768*768);
    k_gemm<<<dim3(6,128),256,SM_BYTES>>>(ah, wh, wl, bproj, tln, tres, NROWS, 768, 768);

    k_lnrow<768,false,true><<<NROWS,256>>>(tres, ln2g, ln2b, nullptr);
    k_wsplit<<<9216,256>>>(fc1w, (size_t)768*3072);
    k_gemm<<<dim3(24,128),256,SM_BYTES>>>(ah, wh, wl, fc1b, nullptr, u1, NROWS, 3072, 768);
    k_lnrow<3072,true,false><<<NROWS,256>>>(u1, mln1g, mln1b, u1g);
    k_dw<<<dim3(12,32,16),256>>>(u1g, dww, dwb);
    k_wsplit<<<9216,256>>>(fc2w, (size_t)3072*768);
    k_gemm<<<dim3(6,128),256,SM_BYTES>>>(ah, wh, wl, fc2b, nullptr, u2, NROWS, 768, 3072);
    k_lnrow<768,false,false><<<NROWS,256>>>(u2, mln2g, mln2b, uln);
    k_final<<<tr,t32x8>>>(out);
    (void)n_in; (void)out_size;
}